// round 3
// baseline (speedup 1.0000x reference)
#include <cuda_runtime.h>
#include <mma.h>

using namespace nvcuda;

// Problem constants
#define B_  2
#define T_  4096
#define H_  8
#define D_  64
#define C_  64
#define NC_ (T_/C_)            // 64
#define BH_ (B_*H_)            // 16
#define ROWSTRIDE (H_*D_)      // 512

// Scratch: per-(bh,chunk) DxD matrix (pass1 sums -> pass2 exclusive prefix).
__device__ float g_S[(size_t)BH_ * NC_ * D_ * D_];

typedef wmma::fragment<wmma::matrix_a, 16, 16, 8, wmma::precision::tf32, wmma::row_major> FragAR;
typedef wmma::fragment<wmma::matrix_a, 16, 16, 8, wmma::precision::tf32, wmma::col_major> FragAC;
typedef wmma::fragment<wmma::matrix_b, 16, 16, 8, wmma::precision::tf32, wmma::row_major> FragBR;
typedef wmma::fragment<wmma::matrix_b, 16, 16, 8, wmma::precision::tf32, wmma::col_major> FragBC;
typedef wmma::fragment<wmma::accumulator, 16, 16, 8, float> FragAcc;

__device__ __forceinline__ void split_tf32(float x, float& hi, float& lo) {
    hi = wmma::__float_to_tf32(x);
    lo = wmma::__float_to_tf32(x - hi);
}
__device__ __forceinline__ void split4(float4 x, float4& hi, float4& lo) {
    split_tf32(x.x, hi.x, lo.x);
    split_tf32(x.y, hi.y, lo.y);
    split_tf32(x.z, hi.z, lo.z);
    split_tf32(x.w, hi.w, lo.w);
}

// 3-term split mma: acc += A*B with (ahi+alo)*(bhi+blo) ~= ahi*bhi + ahi*blo + alo*bhi
#define MMA3(acc, ahi, alo, bhi, blo)            \
    do {                                         \
        wmma::mma_sync(acc, ahi, bhi, acc);      \
        wmma::mma_sync(acc, ahi, blo, acc);      \
        wmma::mma_sync(acc, alo, bhi, acc);      \
    } while (0)

// ---------------------------------------------------------------------------
// Pass 1: S[d][e] = sum_s V[s][d] * K[s][e]  per (bh, chunk).
// 256 threads = 8 warps; warp (wr, wc) computes rows d0=wr*16, cols e0=wc*32.
// A = V^T (col-major over V[s][d]), B = K (row-major).
// ---------------------------------------------------------------------------
#define SMEM1_BYTES (4 * C_ * D_ * (int)sizeof(float))   // 65536

__global__ void __launch_bounds__(256) chunk_sum_kernel(const float* __restrict__ k,
                                                        const float* __restrict__ v) {
    extern __shared__ float sm1[];
    float* Vhi = sm1;
    float* Vlo = Vhi + C_ * D_;
    float* Khi = Vlo + C_ * D_;
    float* Klo = Khi + C_ * D_;

    int blk = blockIdx.x;             // [0, 1024)
    int bh  = blk >> 6;
    int c   = blk & (NC_ - 1);
    int b   = bh >> 3, h = bh & 7;
    int tid = threadIdx.x;

    const float* kbase = k + (((size_t)b * T_ + (size_t)c * C_) * H_ + h) * D_;
    const float* vbase = v + (((size_t)b * T_ + (size_t)c * C_) * H_ + h) * D_;

    #pragma unroll
    for (int f = tid; f < C_ * D_ / 4; f += 256) {
        int s = f >> 4;
        int c4 = f & 15;
        float4 hi, lo;
        float4 kv = *(const float4*)(kbase + (size_t)s * ROWSTRIDE + c4 * 4);
        split4(kv, hi, lo);
        ((float4*)Khi)[f] = hi; ((float4*)Klo)[f] = lo;
        float4 vv = *(const float4*)(vbase + (size_t)s * ROWSTRIDE + c4 * 4);
        split4(vv, hi, lo);
        ((float4*)Vhi)[f] = hi; ((float4*)Vlo)[f] = lo;
    }
    __syncthreads();

    int wid = tid >> 5;
    int d0 = (wid >> 1) * 16;
    int e0 = (wid & 1) * 32;

    FragAcc acc0, acc1;
    wmma::fill_fragment(acc0, 0.f);
    wmma::fill_fragment(acc1, 0.f);

    #pragma unroll
    for (int kk = 0; kk < 8; kk++) {
        int s0 = kk * 8;
        FragAC ahi, alo;
        wmma::load_matrix_sync(ahi, &Vhi[s0 * D_ + d0], D_);   // A(d,s)=V[s][d]
        wmma::load_matrix_sync(alo, &Vlo[s0 * D_ + d0], D_);
        FragBR bhi, blo;
        wmma::load_matrix_sync(bhi, &Khi[s0 * D_ + e0], D_);   // B(s,e)=K[s][e]
        wmma::load_matrix_sync(blo, &Klo[s0 * D_ + e0], D_);
        MMA3(acc0, ahi, alo, bhi, blo);
        wmma::load_matrix_sync(bhi, &Khi[s0 * D_ + e0 + 16], D_);
        wmma::load_matrix_sync(blo, &Klo[s0 * D_ + e0 + 16], D_);
        MMA3(acc1, ahi, alo, bhi, blo);
    }

    float* Sout = g_S + (size_t)blk * D_ * D_;
    wmma::store_matrix_sync(&Sout[d0 * D_ + e0],      acc0, D_, wmma::mem_row_major);
    wmma::store_matrix_sync(&Sout[d0 * D_ + e0 + 16], acc1, D_, wmma::mem_row_major);
}

// ---------------------------------------------------------------------------
// Pass 2: in-place EXCLUSIVE prefix over the chunk axis for every (bh, d, e).
// ---------------------------------------------------------------------------
__global__ void __launch_bounds__(256) prefix_kernel() {
    int gidx = blockIdx.x * 256 + threadIdx.x;   // [0, BH_*D_*D_)
    int bh  = gidx >> 12;
    int idx = gidx & 4095;
    float* base = g_S + (size_t)bh * NC_ * D_ * D_ + idx;

    float vals[NC_];
    #pragma unroll
    for (int c = 0; c < NC_; c++) vals[c] = base[(size_t)c * D_ * D_];
    float run = 0.f;
    #pragma unroll
    for (int c = 0; c < NC_; c++) { float t = vals[c]; vals[c] = run; run += t; }
    #pragma unroll
    for (int c = 0; c < NC_; c++) base[(size_t)c * D_ * D_] = vals[c];
}

// ---------------------------------------------------------------------------
// Pass 3: Y = tril(Q K^T) V + Q M_prev^T per (bh, chunk).
// 256 threads = 8 warps; warp (wr, wc): rows t0=wr*16, cols n0=wc*32.
// U buffer is reused: K (hi/lo) -> raw scores -> masked A (hi/lo) -> M (hi/lo).
// ---------------------------------------------------------------------------
#define SMEM3_BYTES (6 * C_ * D_ * (int)sizeof(float))   // 98304

__global__ void __launch_bounds__(256) output_kernel(const float* __restrict__ q,
                                                     const float* __restrict__ k,
                                                     const float* __restrict__ v,
                                                     float* __restrict__ y) {
    extern __shared__ float sm[];
    float* Qhi = sm;
    float* Qlo = Qhi + C_ * D_;
    float* Uhi = Qlo + C_ * D_;
    float* Ulo = Uhi + C_ * D_;
    float* Vhi = Ulo + C_ * D_;
    float* Vlo = Vhi + C_ * D_;

    int blk = blockIdx.x;             // [0, 1024)
    int bh  = blk >> 6;
    int c   = blk & (NC_ - 1);
    int b   = bh >> 3, h = bh & 7;
    int tid = threadIdx.x;

    const float* qbase = q + (((size_t)b * T_ + (size_t)c * C_) * H_ + h) * D_;
    const float* kbase = k + (((size_t)b * T_ + (size_t)c * C_) * H_ + h) * D_;
    const float* vbase = v + (((size_t)b * T_ + (size_t)c * C_) * H_ + h) * D_;
    const float* Mbase = g_S + (size_t)blk * D_ * D_;

    #pragma unroll
    for (int f = tid; f < C_ * D_ / 4; f += 256) {
        int s = f >> 4;
        int c4 = f & 15;
        float4 hi, lo;
        float4 qv = *(const float4*)(qbase + (size_t)s * ROWSTRIDE + c4 * 4);
        split4(qv, hi, lo);
        ((float4*)Qhi)[f] = hi; ((float4*)Qlo)[f] = lo;
        float4 kv = *(const float4*)(kbase + (size_t)s * ROWSTRIDE + c4 * 4);
        split4(kv, hi, lo);
        ((float4*)Uhi)[f] = hi; ((float4*)Ulo)[f] = lo;
        float4 vv = *(const float4*)(vbase + (size_t)s * ROWSTRIDE + c4 * 4);
        split4(vv, hi, lo);
        ((float4*)Vhi)[f] = hi; ((float4*)Vlo)[f] = lo;
    }
    __syncthreads();

    int wid = tid >> 5;
    int t0 = (wid >> 1) * 16;
    int n0 = (wid & 1) * 32;

    // ---- Scores: S[t][s] = sum_e Q[t][e] K[s][e];  B = K^T (col-major over K[s][e])
    FragAcc acc0, acc1;
    wmma::fill_fragment(acc0, 0.f);
    wmma::fill_fragment(acc1, 0.f);
    #pragma unroll
    for (int kk = 0; kk < 8; kk++) {
        int e0 = kk * 8;
        FragAR ahi, alo;
        wmma::load_matrix_sync(ahi, &Qhi[t0 * D_ + e0], D_);
        wmma::load_matrix_sync(alo, &Qlo[t0 * D_ + e0], D_);
        FragBC bhi, blo;
        wmma::load_matrix_sync(bhi, &Uhi[n0 * D_ + e0], D_);          // B(e,s)=K[s][e]
        wmma::load_matrix_sync(blo, &Ulo[n0 * D_ + e0], D_);
        MMA3(acc0, ahi, alo, bhi, blo);
        wmma::load_matrix_sync(bhi, &Uhi[(n0 + 16) * D_ + e0], D_);
        wmma::load_matrix_sync(blo, &Ulo[(n0 + 16) * D_ + e0], D_);
        MMA3(acc1, ahi, alo, bhi, blo);
    }
    __syncthreads();   // everyone done reading K from U
    wmma::store_matrix_sync(&Uhi[t0 * D_ + n0],      acc0, D_, wmma::mem_row_major);
    wmma::store_matrix_sync(&Uhi[t0 * D_ + n0 + 16], acc1, D_, wmma::mem_row_major);
    __syncthreads();

    // ---- Causal mask (s <= t) + tf32 split, in place
    #pragma unroll
    for (int f = tid; f < C_ * D_; f += 256) {
        int t = f >> 6, s = f & 63;
        float x = (s <= t) ? Uhi[f] : 0.f;
        float hi, lo;
        split_tf32(x, hi, lo);
        Uhi[f] = hi; Ulo[f] = lo;
    }
    __syncthreads();

    // ---- B1: Y[t][d] += sum_s A[t][s] V[s][d]
    wmma::fill_fragment(acc0, 0.f);
    wmma::fill_fragment(acc1, 0.f);
    #pragma unroll
    for (int kk = 0; kk < 8; kk++) {
        int s0 = kk * 8;
        FragAR ahi, alo;
        wmma::load_matrix_sync(ahi, &Uhi[t0 * D_ + s0], D_);
        wmma::load_matrix_sync(alo, &Ulo[t0 * D_ + s0], D_);
        FragBR bhi, blo;
        wmma::load_matrix_sync(bhi, &Vhi[s0 * D_ + n0], D_);
        wmma::load_matrix_sync(blo, &Vlo[s0 * D_ + n0], D_);
        MMA3(acc0, ahi, alo, bhi, blo);
        wmma::load_matrix_sync(bhi, &Vhi[s0 * D_ + n0 + 16], D_);
        wmma::load_matrix_sync(blo, &Vlo[s0 * D_ + n0 + 16], D_);
        MMA3(acc1, ahi, alo, bhi, blo);
    }
    __syncthreads();   // A consumed; reuse U for M

    // ---- Load M (L2-resident), split into U
    #pragma unroll
    for (int f = tid; f < D_ * D_ / 4; f += 256) {
        float4 hi, lo;
        float4 mv = *(const float4*)(Mbase + f * 4);
        split4(mv, hi, lo);
        ((float4*)Uhi)[f] = hi; ((float4*)Ulo)[f] = lo;
    }
    __syncthreads();

    // ---- B2: Y[t][d] += sum_e Q[t][e] M[d][e];  B = M^T (col-major over M[d][e])
    #pragma unroll
    for (int kk = 0; kk < 8; kk++) {
        int e0 = kk * 8;
        FragAR ahi, alo;
        wmma::load_matrix_sync(ahi, &Qhi[t0 * D_ + e0], D_);
        wmma::load_matrix_sync(alo, &Qlo[t0 * D_ + e0], D_);
        FragBC bhi, blo;
        wmma::load_matrix_sync(bhi, &Uhi[n0 * D_ + e0], D_);          // B(e,d)=M[d][e]
        wmma::load_matrix_sync(blo, &Ulo[n0 * D_ + e0], D_);
        MMA3(acc0, ahi, alo, bhi, blo);
        wmma::load_matrix_sync(bhi, &Uhi[(n0 + 16) * D_ + e0], D_);
        wmma::load_matrix_sync(blo, &Ulo[(n0 + 16) * D_ + e0], D_);
        MMA3(acc1, ahi, alo, bhi, blo);
    }

    float* ybase = y + (((size_t)b * T_ + (size_t)c * C_) * H_ + h) * D_;
    wmma::store_matrix_sync(ybase + (size_t)t0 * ROWSTRIDE + n0,      acc0, ROWSTRIDE,
                            wmma::mem_row_major);
    wmma::store_matrix_sync(ybase + (size_t)t0 * ROWSTRIDE + n0 + 16, acc1, ROWSTRIDE,
                            wmma::mem_row_major);
}

// ---------------------------------------------------------------------------
extern "C" void kernel_launch(void* const* d_in, const int* in_sizes, int n_in,
                              void* d_out, int out_size) {
    (void)in_sizes; (void)n_in; (void)out_size;
    const float* q = (const float*)d_in[0];
    const float* k = (const float*)d_in[1];
    const float* v = (const float*)d_in[2];
    float* y = (float*)d_out;

    cudaFuncSetAttribute(chunk_sum_kernel, cudaFuncAttributeMaxDynamicSharedMemorySize,
                         SMEM1_BYTES);
    cudaFuncSetAttribute(output_kernel, cudaFuncAttributeMaxDynamicSharedMemorySize,
                         SMEM3_BYTES);

    chunk_sum_kernel<<<BH_ * NC_, 256, SMEM1_BYTES>>>(k, v);
    prefix_kernel<<<(BH_ * D_ * D_) / 256, 256>>>();
    output_kernel<<<BH_ * NC_, 256, SMEM3_BYTES>>>(q, k, v, y);
}

// round 4
// speedup vs baseline: 3.6409x; 3.6409x over previous
#include <cuda_runtime.h>
#include <cuda_bf16.h>
#include <mma.h>

using namespace nvcuda;
typedef __nv_bfloat16 bf16;

// Problem constants
#define B_  2
#define T_  4096
#define H_  8
#define D_  64
#define C_  64
#define NC_ (T_/C_)            // 64
#define BH_ (B_*H_)            // 16
#define ROWSTRIDE (H_*D_)      // 512
#define SB_ 72                 // bf16 smem row stride: 144B -> 4-bank shift/row, LDSM conflict-free
#define SRS_ 72                // fp32 score-scratch stride

// Scratch: per-(bh,chunk) DxD fp32 matrix (pass1 sums -> pass2 exclusive prefix).
__device__ float g_S[(size_t)BH_ * NC_ * D_ * D_];

typedef wmma::fragment<wmma::matrix_a, 16, 16, 16, bf16, wmma::row_major> FragAR;
typedef wmma::fragment<wmma::matrix_a, 16, 16, 16, bf16, wmma::col_major> FragAC;
typedef wmma::fragment<wmma::matrix_b, 16, 16, 16, bf16, wmma::row_major> FragBR;
typedef wmma::fragment<wmma::matrix_b, 16, 16, 16, bf16, wmma::col_major> FragBC;
typedef wmma::fragment<wmma::accumulator, 16, 16, 16, float> FragAcc;

// 3-term split mma: (ahi+alo)*(bhi+blo) ~= ahi*bhi + ahi*blo + alo*bhi
#define MMA3(acc, ahi, alo, bhi, blo)            \
    do {                                         \
        wmma::mma_sync(acc, ahi, bhi, acc);      \
        wmma::mma_sync(acc, ahi, blo, acc);      \
        wmma::mma_sync(acc, alo, bhi, acc);      \
    } while (0)

// Split 4 fp32 into bf16 hi/lo quads and store (8B stores, addresses 8B-aligned).
__device__ __forceinline__ void split_store4(bf16* HI, bf16* LO, int idx, float4 x) {
    float hx = __bfloat162float(__float2bfloat16(x.x));
    float hy = __bfloat162float(__float2bfloat16(x.y));
    float hz = __bfloat162float(__float2bfloat16(x.z));
    float hw = __bfloat162float(__float2bfloat16(x.w));
    __nv_bfloat162 h01 = __floats2bfloat162_rn(x.x, x.y);
    __nv_bfloat162 h23 = __floats2bfloat162_rn(x.z, x.w);
    __nv_bfloat162 l01 = __floats2bfloat162_rn(x.x - hx, x.y - hy);
    __nv_bfloat162 l23 = __floats2bfloat162_rn(x.z - hz, x.w - hw);
    uint2 hh, ll;
    hh.x = *(unsigned*)&h01; hh.y = *(unsigned*)&h23;
    ll.x = *(unsigned*)&l01; ll.y = *(unsigned*)&l23;
    *(uint2*)&HI[idx] = hh;
    *(uint2*)&LO[idx] = ll;
}

__device__ __forceinline__ void split_scalar(float x, bf16& hi, bf16& lo) {
    hi = __float2bfloat16(x);
    lo = __float2bfloat16(x - __bfloat162float(hi));
}

// ---------------------------------------------------------------------------
// Pass 1: S[d][e] = sum_s V[s][d] * K[s][e]  per (bh, chunk).
// 8 warps; warp (wr, wc): rows d0=wr*16, cols e0=wc*32.
// A = V^T (col-major over V[s][d]), B = K (row-major). bf16 hi/lo split.
// ---------------------------------------------------------------------------
#define SMEM1_BYTES (4 * C_ * SB_ * (int)sizeof(bf16))   // 36864

__global__ void __launch_bounds__(256) chunk_sum_kernel(const float* __restrict__ k,
                                                        const float* __restrict__ v) {
    extern __shared__ __align__(16) char smraw1[];
    bf16* Vhi = (bf16*)smraw1;
    bf16* Vlo = Vhi + C_ * SB_;
    bf16* Khi = Vlo + C_ * SB_;
    bf16* Klo = Khi + C_ * SB_;

    int blk = blockIdx.x;             // [0, 1024)
    int bh  = blk >> 6;
    int c   = blk & (NC_ - 1);
    int b   = bh >> 3, h = bh & 7;
    int tid = threadIdx.x;

    const float* kbase = k + (((size_t)b * T_ + (size_t)c * C_) * H_ + h) * D_;
    const float* vbase = v + (((size_t)b * T_ + (size_t)c * C_) * H_ + h) * D_;

    #pragma unroll
    for (int f = tid; f < C_ * D_ / 4; f += 256) {
        int s = f >> 4;
        int cc = (f & 15) * 4;
        split_store4(Khi, Klo, s * SB_ + cc,
                     *(const float4*)(kbase + (size_t)s * ROWSTRIDE + cc));
        split_store4(Vhi, Vlo, s * SB_ + cc,
                     *(const float4*)(vbase + (size_t)s * ROWSTRIDE + cc));
    }
    __syncthreads();

    int wid = tid >> 5;
    int d0 = (wid >> 1) * 16;
    int e0 = (wid & 1) * 32;

    FragAcc acc0, acc1;
    wmma::fill_fragment(acc0, 0.f);
    wmma::fill_fragment(acc1, 0.f);

    #pragma unroll
    for (int kk = 0; kk < 4; kk++) {
        int s0 = kk * 16;
        FragAC ahi, alo;
        wmma::load_matrix_sync(ahi, &Vhi[s0 * SB_ + d0], SB_);   // A(d,s)=V[s][d]
        wmma::load_matrix_sync(alo, &Vlo[s0 * SB_ + d0], SB_);
        FragBR bhi, blo;
        wmma::load_matrix_sync(bhi, &Khi[s0 * SB_ + e0], SB_);   // B(s,e)=K[s][e]
        wmma::load_matrix_sync(blo, &Klo[s0 * SB_ + e0], SB_);
        MMA3(acc0, ahi, alo, bhi, blo);
        wmma::load_matrix_sync(bhi, &Khi[s0 * SB_ + e0 + 16], SB_);
        wmma::load_matrix_sync(blo, &Klo[s0 * SB_ + e0 + 16], SB_);
        MMA3(acc1, ahi, alo, bhi, blo);
    }

    float* Sout = g_S + (size_t)blk * D_ * D_;
    wmma::store_matrix_sync(&Sout[d0 * D_ + e0],      acc0, D_, wmma::mem_row_major);
    wmma::store_matrix_sync(&Sout[d0 * D_ + e0 + 16], acc1, D_, wmma::mem_row_major);
}

// ---------------------------------------------------------------------------
// Pass 2: in-place EXCLUSIVE prefix over the chunk axis for every (bh, d, e).
// ---------------------------------------------------------------------------
__global__ void __launch_bounds__(256) prefix_kernel() {
    int gidx = blockIdx.x * 256 + threadIdx.x;   // [0, BH_*D_*D_)
    int bh  = gidx >> 12;
    int idx = gidx & 4095;
    float* base = g_S + (size_t)bh * NC_ * D_ * D_ + idx;

    float vals[NC_];
    #pragma unroll
    for (int c = 0; c < NC_; c++) vals[c] = base[(size_t)c * D_ * D_];
    float run = 0.f;
    #pragma unroll
    for (int c = 0; c < NC_; c++) { float t = vals[c]; vals[c] = run; run += t; }
    #pragma unroll
    for (int c = 0; c < NC_; c++) base[(size_t)c * D_ * D_] = vals[c];
}

// ---------------------------------------------------------------------------
// Pass 3: Y = tril(Q K^T) V + Q M_prev^T per (bh, chunk).
// 8 warps; warp (wr, wc): rows t0=wr*16, cols n0=wc*32.
// U (bf16 hi/lo) reused: K -> masked A -> M.  Sraw: fp32 score scratch.
// ---------------------------------------------------------------------------
#define SMEM3_BYTES (6 * C_ * SB_ * (int)sizeof(bf16) + C_ * SRS_ * (int)sizeof(float)) // 73728

__global__ void __launch_bounds__(256) output_kernel(const float* __restrict__ q,
                                                     const float* __restrict__ k,
                                                     const float* __restrict__ v,
                                                     float* __restrict__ y) {
    extern __shared__ __align__(16) char smraw[];
    bf16* Qhi = (bf16*)smraw;
    bf16* Qlo = Qhi + C_ * SB_;
    bf16* Uhi = Qlo + C_ * SB_;
    bf16* Ulo = Uhi + C_ * SB_;
    bf16* Vhi = Ulo + C_ * SB_;
    bf16* Vlo = Vhi + C_ * SB_;
    float* Sraw = (float*)(Vlo + C_ * SB_);

    int blk = blockIdx.x;             // [0, 1024)
    int bh  = blk >> 6;
    int c   = blk & (NC_ - 1);
    int b   = bh >> 3, h = bh & 7;
    int tid = threadIdx.x;

    const float* qbase = q + (((size_t)b * T_ + (size_t)c * C_) * H_ + h) * D_;
    const float* kbase = k + (((size_t)b * T_ + (size_t)c * C_) * H_ + h) * D_;
    const float* vbase = v + (((size_t)b * T_ + (size_t)c * C_) * H_ + h) * D_;
    const float* Mbase = g_S + (size_t)blk * D_ * D_;

    #pragma unroll
    for (int f = tid; f < C_ * D_ / 4; f += 256) {
        int s = f >> 4;
        int cc = (f & 15) * 4;
        split_store4(Qhi, Qlo, s * SB_ + cc,
                     *(const float4*)(qbase + (size_t)s * ROWSTRIDE + cc));
        split_store4(Uhi, Ulo, s * SB_ + cc,
                     *(const float4*)(kbase + (size_t)s * ROWSTRIDE + cc));
        split_store4(Vhi, Vlo, s * SB_ + cc,
                     *(const float4*)(vbase + (size_t)s * ROWSTRIDE + cc));
    }
    __syncthreads();

    int wid = tid >> 5;
    int t0 = (wid >> 1) * 16;
    int n0 = (wid & 1) * 32;

    // ---- Scores: S[t][s] = sum_e Q[t][e] K[s][e];  B = K^T (col-major over K[s][e])
    FragAcc acc0, acc1;
    wmma::fill_fragment(acc0, 0.f);
    wmma::fill_fragment(acc1, 0.f);
    #pragma unroll
    for (int kk = 0; kk < 4; kk++) {
        int e0 = kk * 16;
        FragAR ahi, alo;
        wmma::load_matrix_sync(ahi, &Qhi[t0 * SB_ + e0], SB_);
        wmma::load_matrix_sync(alo, &Qlo[t0 * SB_ + e0], SB_);
        FragBC bhi, blo;
        wmma::load_matrix_sync(bhi, &Uhi[n0 * SB_ + e0], SB_);        // B(e,s)=K[s][e]
        wmma::load_matrix_sync(blo, &Ulo[n0 * SB_ + e0], SB_);
        MMA3(acc0, ahi, alo, bhi, blo);
        wmma::load_matrix_sync(bhi, &Uhi[(n0 + 16) * SB_ + e0], SB_);
        wmma::load_matrix_sync(blo, &Ulo[(n0 + 16) * SB_ + e0], SB_);
        MMA3(acc1, ahi, alo, bhi, blo);
    }
    __syncthreads();   // all K reads from U complete
    wmma::store_matrix_sync(&Sraw[t0 * SRS_ + n0],      acc0, SRS_, wmma::mem_row_major);
    wmma::store_matrix_sync(&Sraw[t0 * SRS_ + n0 + 16], acc1, SRS_, wmma::mem_row_major);
    __syncthreads();

    // ---- Causal mask (s <= t) + bf16 split into U
    #pragma unroll
    for (int f = tid; f < C_ * D_; f += 256) {
        int t = f >> 6, s = f & 63;
        float x = (s <= t) ? Sraw[t * SRS_ + s] : 0.f;
        bf16 hi, lo;
        split_scalar(x, hi, lo);
        Uhi[t * SB_ + s] = hi;
        Ulo[t * SB_ + s] = lo;
    }
    __syncthreads();

    // ---- B1: Y[t][d] += sum_s A[t][s] V[s][d]
    wmma::fill_fragment(acc0, 0.f);
    wmma::fill_fragment(acc1, 0.f);
    #pragma unroll
    for (int kk = 0; kk < 4; kk++) {
        int s0 = kk * 16;
        FragAR ahi, alo;
        wmma::load_matrix_sync(ahi, &Uhi[t0 * SB_ + s0], SB_);
        wmma::load_matrix_sync(alo, &Ulo[t0 * SB_ + s0], SB_);
        FragBR bhi, blo;
        wmma::load_matrix_sync(bhi, &Vhi[s0 * SB_ + n0], SB_);
        wmma::load_matrix_sync(blo, &Vlo[s0 * SB_ + n0], SB_);
        MMA3(acc0, ahi, alo, bhi, blo);
        wmma::load_matrix_sync(bhi, &Vhi[s0 * SB_ + n0 + 16], SB_);
        wmma::load_matrix_sync(blo, &Vlo[s0 * SB_ + n0 + 16], SB_);
        MMA3(acc1, ahi, alo, bhi, blo);
    }
    __syncthreads();   // A consumed; reuse U for M

    // ---- Load M (L2-resident) split into U, layout [d][e]
    #pragma unroll
    for (int f = tid; f < D_ * D_ / 4; f += 256) {
        int d = f >> 4;
        int cc = (f & 15) * 4;
        split_store4(Uhi, Ulo, d * SB_ + cc, *(const float4*)(Mbase + f * 4));
    }
    __syncthreads();

    // ---- B2: Y[t][d] += sum_e Q[t][e] M[d][e];  B = M^T (col-major over M[d][e])
    #pragma unroll
    for (int kk = 0; kk < 4; kk++) {
        int e0 = kk * 16;
        FragAR ahi, alo;
        wmma::load_matrix_sync(ahi, &Qhi[t0 * SB_ + e0], SB_);
        wmma::load_matrix_sync(alo, &Qlo[t0 * SB_ + e0], SB_);
        FragBC bhi, blo;
        wmma::load_matrix_sync(bhi, &Uhi[n0 * SB_ + e0], SB_);        // B(e,d)=M[d][e]
        wmma::load_matrix_sync(blo, &Ulo[n0 * SB_ + e0], SB_);
        MMA3(acc0, ahi, alo, bhi, blo);
        wmma::load_matrix_sync(bhi, &Uhi[(n0 + 16) * SB_ + e0], SB_);
        wmma::load_matrix_sync(blo, &Ulo[(n0 + 16) * SB_ + e0], SB_);
        MMA3(acc1, ahi, alo, bhi, blo);
    }

    float* ybase = y + (((size_t)b * T_ + (size_t)c * C_) * H_ + h) * D_;
    wmma::store_matrix_sync(ybase + (size_t)t0 * ROWSTRIDE + n0,      acc0, ROWSTRIDE,
                            wmma::mem_row_major);
    wmma::store_matrix_sync(ybase + (size_t)t0 * ROWSTRIDE + n0 + 16, acc1, ROWSTRIDE,
                            wmma::mem_row_major);
}

// ---------------------------------------------------------------------------
extern "C" void kernel_launch(void* const* d_in, const int* in_sizes, int n_in,
                              void* d_out, int out_size) {
    (void)in_sizes; (void)n_in; (void)out_size;
    const float* q = (const float*)d_in[0];
    const float* k = (const float*)d_in[1];
    const float* v = (const float*)d_in[2];
    float* y = (float*)d_out;

    cudaFuncSetAttribute(chunk_sum_kernel, cudaFuncAttributeMaxDynamicSharedMemorySize,
                         SMEM1_BYTES);
    cudaFuncSetAttribute(output_kernel, cudaFuncAttributeMaxDynamicSharedMemorySize,
                         SMEM3_BYTES);

    chunk_sum_kernel<<<BH_ * NC_, 256, SMEM1_BYTES>>>(k, v);
    prefix_kernel<<<(BH_ * D_ * D_) / 256, 256>>>();
    output_kernel<<<BH_ * NC_, 256, SMEM3_BYTES>>>(q, k, v, y);
}